// round 16
// baseline (speedup 1.0000x reference)
#include <cuda_runtime.h>
#include <cuda_fp16.h>
#include <cstdint>
#include <cstddef>

#define N_USERS 100000
#define N_ITEMS 50000
#define NTOT    150000
#define D       64
#define NNZ     2000000
#define BSZ     16384
#define BITW    ((NTOT + 31) / 32)
#define RW      (D / 4)                      // uint2 (4 halves) per row = 16
#define CAPLG   6
#define CAP     (1 << CAPLG)                 // 64 slots/row; max degree ~38

// Scratch (allocation-free rule: __device__ globals, zero-init at load)
__device__ uint2    d_h0[(size_t)NTOT * RW];    // fp16 concat(embU, embI)
__device__ uint2    d_h1[(size_t)NTOT * RW];
__device__ uint2    d_h2[(size_t)NTOT * RW];
__device__ float4   d_light[(size_t)NTOT * RW]; // fp32 light embedding (bitmap rows)
__device__ unsigned d_bitmap[BITW];
__device__ int      d_cnt[NTOT];                // zeroed by spmm<2> each call
__device__ int2     d_epack[(size_t)NTOT * CAP];// padded CSR {col*RW, bitcast(val)}

// ---------------------------------------------------------------------------
// Kernel 1 (fused build): bitmap clear + padded-CSR bucket scatter (atomic
// rank per edge, slot = row*CAP + rank) + fp32->fp16 conversion of e0.
// start[r] == r*CAP by construction: no hist/scan passes.
// ---------------------------------------------------------------------------
__global__ __launch_bounds__(256) void build_kernel(const int4*   __restrict__ grow4,
                                                    const int4*   __restrict__ gcol4,
                                                    const float4* __restrict__ gval4,
                                                    const float2* __restrict__ embU2,
                                                    const float2* __restrict__ embI2) {
    int i = blockIdx.x * blockDim.x + threadIdx.x;
    if (i < BITW) d_bitmap[i] = 0u;
    if (i < NNZ / 4) {
        int4   r = __ldg(grow4 + i);
        int4   c = __ldg(gcol4 + i);
        float4 v = __ldg(gval4 + i);
        int p0 = atomicAdd(&d_cnt[r.x], 1);
        int p1 = atomicAdd(&d_cnt[r.y], 1);
        int p2 = atomicAdd(&d_cnt[r.z], 1);
        int p3 = atomicAdd(&d_cnt[r.w], 1);
        d_epack[((size_t)r.x << CAPLG) + p0] = make_int2(c.x * RW, __float_as_int(v.x));
        d_epack[((size_t)r.y << CAPLG) + p1] = make_int2(c.y * RW, __float_as_int(v.y));
        d_epack[((size_t)r.z << CAPLG) + p2] = make_int2(c.z * RW, __float_as_int(v.z));
        d_epack[((size_t)r.w << CAPLG) + p3] = make_int2(c.w * RW, __float_as_int(v.w));
    }
    // e0 conversion: one uint2 = 4 halves = 2 float2 loads
    const int HTOT = NTOT * RW;                 // 2.4M uint2
    const int USPLIT = N_USERS * RW;
    int nth = gridDim.x * blockDim.x;
    for (int k = i; k < HTOT; k += nth) {
        float2 a, b;
        if (k < USPLIT) { a = __ldg(embU2 + 2 * k);            b = __ldg(embU2 + 2 * k + 1); }
        else            { a = __ldg(embI2 + 2 * (k - USPLIT)); b = __ldg(embI2 + 2 * (k - USPLIT) + 1); }
        __half2 h0 = __float22half2_rn(a);
        __half2 h1 = __float22half2_rn(b);
        uint2 q;
        q.x = *reinterpret_cast<unsigned*>(&h0);
        q.y = *reinterpret_cast<unsigned*>(&h1);
        d_h0[k] = q;
    }
}

// ---------------------------------------------------------------------------
// Row-parallel SpMM over padded CSR on fp16 features: 16 lanes per row
// (2 rows per warp), one uint2 (8B) per lane per gather. fp32 accumulation.
// Main path (cnt <= 16, ~82% of rows): ALL epack entries prefetched with
// predicated loads, then ALL 16 gathers issued with no interleaved
// dependencies -> one ~2x250cyc exposure per row instead of two. Predicated
// (not clamped) loads: dead slots cost zero traffic. Overflow rows loop.
// MODE 0: h0->h1 (+ folded bitmap mark)
// MODE 1: h1->h2
// MODE 2: h2 -> fused LIGHT epilogue for bitmap rows; also re-zeroes d_cnt.
// ---------------------------------------------------------------------------
template <int MODE>
__global__ __launch_bounds__(256) void spmm_csr_kernel(const float4* __restrict__ embU4,
                                                       const float4* __restrict__ embI4,
                                                       const int*    __restrict__ users,
                                                       const int*    __restrict__ items) {
    unsigned gid = blockIdx.x * blockDim.x + threadIdx.x;

    if (MODE == 0) {                            // folded mark (needs 2*BSZ threads)
        if (gid < BSZ) {
            int m = __ldg(users + gid);
            atomicOr(&d_bitmap[m >> 5], 1u << (m & 31));
        } else if (gid < 2 * BSZ) {
            int m = N_USERS + __ldg(items + (gid - BSZ));
            atomicOr(&d_bitmap[m >> 5], 1u << (m & 31));
        }
    }

    unsigned r = gid >> 4;
    if (r >= NTOT) return;
    unsigned lane = gid & 15u;                  // uint2 index within row

    int cnt = __ldg(d_cnt + r);
    if (MODE == 2) {
        if (lane == 0) d_cnt[r] = 0;            // reset for next graph replay
        if (!((d_bitmap[r >> 5] >> (r & 31)) & 1u)) return;
    }

    const uint2* __restrict__ src = (MODE == 0) ? d_h0 : (MODE == 1) ? d_h1 : d_h2;
    const int2*  __restrict__ ep  = d_epack + ((size_t)r << CAPLG);

    float4 acc = make_float4(0.f, 0.f, 0.f, 0.f);

    // ---- main: first up-to-16 edges, fully prefetched, predicated ----
    {
        int2 p[16];
#pragma unroll
        for (int k = 0; k < 16; k++)
            p[k] = (k < cnt) ? __ldg(ep + k) : make_int2(0, 0);

        uint2 qa[8], qb[8];
#pragma unroll
        for (int k = 0; k < 8; k++)
            qa[k] = (k < cnt) ? __ldg(src + (size_t)p[k].x + lane) : make_uint2(0u, 0u);
#pragma unroll
        for (int k = 0; k < 8; k++)
            qb[k] = (8 + k < cnt) ? __ldg(src + (size_t)p[8 + k].x + lane) : make_uint2(0u, 0u);

#pragma unroll
        for (int k = 0; k < 8; k++) {
            float v = __int_as_float(p[k].y);   // 0.0f for dead slots
            float2 a = __half22float2(*reinterpret_cast<__half2*>(&qa[k].x));
            float2 b = __half22float2(*reinterpret_cast<__half2*>(&qa[k].y));
            acc.x = fmaf(v, a.x, acc.x); acc.y = fmaf(v, a.y, acc.y);
            acc.z = fmaf(v, b.x, acc.z); acc.w = fmaf(v, b.y, acc.w);
        }
#pragma unroll
        for (int k = 0; k < 8; k++) {
            float v = __int_as_float(p[8 + k].y);
            float2 a = __half22float2(*reinterpret_cast<__half2*>(&qb[k].x));
            float2 b = __half22float2(*reinterpret_cast<__half2*>(&qb[k].y));
            acc.x = fmaf(v, a.x, acc.x); acc.y = fmaf(v, a.y, acc.y);
            acc.z = fmaf(v, b.x, acc.z); acc.w = fmaf(v, b.y, acc.w);
        }
    }

    // ---- overflow: rows with cnt > 16 (~18%) ----
    for (int j = 16; j < cnt; j += 8) {
        int2  p[8];
        uint2 q[8];
#pragma unroll
        for (int k = 0; k < 8; k++)
            p[k] = (j + k < cnt) ? __ldg(ep + j + k) : make_int2(0, 0);
#pragma unroll
        for (int k = 0; k < 8; k++)
            q[k] = (j + k < cnt) ? __ldg(src + (size_t)p[k].x + lane) : make_uint2(0u, 0u);
#pragma unroll
        for (int k = 0; k < 8; k++) {
            float v = __int_as_float(p[k].y);
            float2 a = __half22float2(*reinterpret_cast<__half2*>(&q[k].x));
            float2 b = __half22float2(*reinterpret_cast<__half2*>(&q[k].y));
            acc.x = fmaf(v, a.x, acc.x); acc.y = fmaf(v, a.y, acc.y);
            acc.z = fmaf(v, b.x, acc.z); acc.w = fmaf(v, b.y, acc.w);
        }
    }

    if (MODE == 2) {
        // acc = e3 lane slice. Compose light = 0.25*(e0_exact + e1 + e2 + e3).
        size_t idx = (size_t)r * RW + lane;
        float4 e0 = (r < N_USERS)
                  ? __ldg(embU4 + (size_t)r * RW + lane)
                  : __ldg(embI4 + (size_t)(r - N_USERS) * RW + lane);
        uint2 q1 = __ldg(d_h1 + idx);
        uint2 q2 = __ldg(d_h2 + idx);
        float2 a1 = __half22float2(*reinterpret_cast<__half2*>(&q1.x));
        float2 b1 = __half22float2(*reinterpret_cast<__half2*>(&q1.y));
        float2 a2 = __half22float2(*reinterpret_cast<__half2*>(&q2.x));
        float2 b2 = __half22float2(*reinterpret_cast<__half2*>(&q2.y));
        float4 L;
        L.x = 0.25f * (e0.x + a1.x + a2.x + acc.x);
        L.y = 0.25f * (e0.y + a1.y + a2.y + acc.y);
        L.z = 0.25f * (e0.z + b1.x + b2.x + acc.z);
        L.w = 0.25f * (e0.w + b1.y + b2.y + acc.w);
        d_light[idx] = L;
    } else {
        uint2* dst = (MODE == 0) ? d_h1 : d_h2;
        __half2 h0 = __floats2half2_rn(acc.x, acc.y);
        __half2 h1 = __floats2half2_rn(acc.z, acc.w);
        uint2 q;
        q.x = *reinterpret_cast<unsigned*>(&h0);
        q.y = *reinterpret_cast<unsigned*>(&h1);
        dst[(size_t)r * RW + lane] = q;
    }
}

// ---------------------------------------------------------------------------
// Final head: read precomputed fp32 light embeddings, W_u/W_i matvecs,
// softmax, sigmoid, weighted dot.
// ---------------------------------------------------------------------------
__global__ __launch_bounds__(64) void final_kernel(
    const float* __restrict__ wU,   const float* __restrict__ wI,
    const float* __restrict__ x1,   const float* __restrict__ x0,
    const int*   __restrict__ users,const int*   __restrict__ items,
    const int*   __restrict__ xij,  float*       __restrict__ out) {
    __shared__ float sWu[D * D];
    __shared__ float sWi[D * D];
    __shared__ float sa[D * 64];

    int tid = threadIdx.x;
    for (int i = tid; i < D * D; i += 64) {
        sWu[i] = wU[i];
        sWi[i] = wI[i];
    }
    __syncthreads();

    int b  = blockIdx.x * 64 + tid;
    int u  = users[b];
    int it = items[b];

    float vec[D];

    {
        const float4* L = d_light + (size_t)u * RW;
#pragma unroll
        for (int k = 0; k < RW; k++) {
            float4 f = __ldg(L + k);
            vec[4 * k] = f.x; vec[4 * k + 1] = f.y;
            vec[4 * k + 2] = f.z; vec[4 * k + 3] = f.w;
        }
    }

    float amax = -1e30f;
    for (int j = 0; j < D; j++) {
        const float* w = sWu + j * D;
        float a = 0.f;
#pragma unroll
        for (int d = 0; d < D; d++) a = fmaf(vec[d], w[d], a);
        sa[j * 64 + tid] = a;
        amax = fmaxf(amax, a);
    }
    float ssum = 0.f;
    for (int j = 0; j < D; j++) {
        float ex = __expf(sa[j * 64 + tid] - amax);
        sa[j * 64 + tid] = ex;
        ssum += ex;
    }
    float scale = 0.5f / ssum;   // (1 - hx) * softmax

    {
        const float4* L = d_light + (size_t)(N_USERS + it) * RW;
#pragma unroll
        for (int k = 0; k < RW; k++) {
            float4 f = __ldg(L + k);
            vec[4 * k] = f.x; vec[4 * k + 1] = f.y;
            vec[4 * k + 2] = f.z; vec[4 * k + 3] = f.w;
        }
    }

    float res = 0.f;
    for (int j = 0; j < D; j++) {
        const float* w = sWi + j * D;
        float a = 0.f;
#pragma unroll
        for (int d = 0; d < D; d++) a = fmaf(vec[d], w[d], a);
        float sg = 1.f / (1.f + __expf(-a));
        res += sa[j * 64 + tid] * scale * sg;
    }

    float xe = (xij[b] > 0) ? x1[it] : x0[it];
    res += 0.5f * (1.f / (1.f + __expf(-xe)));

    out[b] = res;
}

// ---------------------------------------------------------------------------
extern "C" void kernel_launch(void* const* d_in, const int* in_sizes, int n_in,
                              void* d_out, int out_size) {
    const float* embU  = (const float*)d_in[0];
    const float* embI  = (const float*)d_in[1];
    const float* wU    = (const float*)d_in[2];
    const float* wI    = (const float*)d_in[3];
    const float* x1    = (const float*)d_in[4];
    const float* x0    = (const float*)d_in[5];
    const float* gval  = (const float*)d_in[6];
    const int*   grow  = (const int*)d_in[7];
    const int*   gcol  = (const int*)d_in[8];
    const int*   users = (const int*)d_in[9];
    const int*   items = (const int*)d_in[10];
    const int*   xij   = (const int*)d_in[11];
    float*       out   = (float*)d_out;

    (void)in_sizes; (void)n_in; (void)out_size;

    // Fused build: padded CSR, bitmap clear, e0->fp16.
    // d_cnt is zero on entry (.bss first call; re-zeroed by spmm<2> each call).
    build_kernel<<<(NNZ / 4 + 255) / 256, 256>>>((const int4*)grow,
                                                 (const int4*)gcol,
                                                 (const float4*)gval,
                                                 (const float2*)embU,
                                                 (const float2*)embI);

    // Three row-parallel SpMM layers (16 lanes per row, fp16 features);
    // layer 1 folds bitmap marking, layer 3 folds light epilogue + cnt reset.
    const unsigned total  = (unsigned)NTOT * 16u;
    const unsigned blocks = (total + 255) / 256;
    spmm_csr_kernel<0><<<blocks, 256>>>((const float4*)embU, (const float4*)embI, users, items);
    spmm_csr_kernel<1><<<blocks, 256>>>((const float4*)embU, (const float4*)embI, users, items);
    spmm_csr_kernel<2><<<blocks, 256>>>((const float4*)embU, (const float4*)embI, users, items);

    // Final head
    final_kernel<<<BSZ / 64, 64>>>(wU, wI, x1, x0, users, items, xij, out);
}